// round 2
// baseline (speedup 1.0000x reference)
#include <cuda_runtime.h>
#include <math.h>

// Problem constants
static constexpr int PB  = 2;
static constexpr int PS  = 8192;
static constexpr int PD  = 768;
static constexpr int PH  = 12;
static constexpr int PHD = 64;
static constexpr int PW  = 256;
static constexpr int PDFF= 3072;
static constexpr int NT  = PB * PS;           // 16384 tokens

// ---------------- scratch (static device globals; no allocation) -------------
__device__ float g_h   [NT * PD];   // h (post embed-LN); later reused as x for final MLP
__device__ float g_h2  [NT * PD];
__device__ float g_q   [NT * PD];   // later reused as tmp (gemm outputs)
__device__ float g_k   [NT * PD];   // later reused as src2
__device__ float g_v   [NT * PD];
__device__ float g_a   [NT * PD];
__device__ float g_ff  [NT * PDFF];

// ---------------- block reduce (sum of two values, 256 threads) ---------------
__device__ __forceinline__ void reduce2(float& a, float& b, float* sbuf) {
    int lane = threadIdx.x & 31;
    int wid  = threadIdx.x >> 5;
#pragma unroll
    for (int o = 16; o > 0; o >>= 1) {
        a += __shfl_down_sync(0xffffffffu, a, o);
        b += __shfl_down_sync(0xffffffffu, b, o);
    }
    __syncthreads();
    if (lane == 0) { sbuf[wid] = a; sbuf[8 + wid] = b; }
    __syncthreads();
    if (threadIdx.x < 32) {
        a = (lane < 8) ? sbuf[lane] : 0.f;
        b = (lane < 8) ? sbuf[8 + lane] : 0.f;
#pragma unroll
        for (int o = 4; o > 0; o >>= 1) {
            a += __shfl_down_sync(0xffffffffu, a, o);
            b += __shfl_down_sync(0xffffffffu, b, o);
        }
        if (lane == 0) { sbuf[0] = a; sbuf[8] = b; }
    }
    __syncthreads();
    a = sbuf[0]; b = sbuf[8];
}

// -------- K1: hidden = ln(src,n1,1e-5); h = ln(hidden + pos + tt, emb, 1e-12) --
__global__ void k_embed(const float* __restrict__ src, const float* __restrict__ pos,
                        const float* __restrict__ tt,
                        const float* __restrict__ n1s, const float* __restrict__ n1b,
                        const float* __restrict__ es,  const float* __restrict__ eb,
                        float* __restrict__ out) {
    __shared__ float sbuf[16];
    int row = blockIdx.x;
    int s   = row % PS;
    const float* x = src + (size_t)row * PD;
    int t = threadIdx.x;
    float v0 = x[t], v1 = x[t + 256], v2 = x[t + 512];
    float sum = v0 + v1 + v2;
    float sq  = v0*v0 + v1*v1 + v2*v2;
    reduce2(sum, sq, sbuf);
    float m = sum / PD;
    float var = sq / PD - m * m;
    float r = rsqrtf(var + 1e-5f);
    const float* ps = pos + (size_t)s * PD;
    float y0 = (v0 - m) * r * n1s[t]       + n1b[t]       + ps[t]       + tt[t];
    float y1 = (v1 - m) * r * n1s[t + 256] + n1b[t + 256] + ps[t + 256] + tt[t + 256];
    float y2 = (v2 - m) * r * n1s[t + 512] + n1b[t + 512] + ps[t + 512] + tt[t + 512];
    sum = y0 + y1 + y2;
    sq  = y0*y0 + y1*y1 + y2*y2;
    reduce2(sum, sq, sbuf);
    m = sum / PD;
    var = sq / PD - m * m;
    r = rsqrtf(var + 1e-12f);
    float* o = out + (size_t)row * PD;
    o[t]       = (y0 - m) * r * es[t]       + eb[t];
    o[t + 256] = (y1 - m) * r * es[t + 256] + eb[t + 256];
    o[t + 512] = (y2 - m) * r * es[t + 512] + eb[t + 512];
}

// -------- generic: out = ln(a + b, s, bv, eps) --------------------------------
__global__ void k_add_ln(const float* __restrict__ a, const float* __restrict__ b,
                         const float* __restrict__ sc, const float* __restrict__ bv,
                         float eps, float* __restrict__ out) {
    __shared__ float sbuf[16];
    int row = blockIdx.x;
    int t = threadIdx.x;
    const float* ap = a + (size_t)row * PD;
    const float* bp = b + (size_t)row * PD;
    float y0 = ap[t] + bp[t];
    float y1 = ap[t + 256] + bp[t + 256];
    float y2 = ap[t + 512] + bp[t + 512];
    float sum = y0 + y1 + y2, sq = y0*y0 + y1*y1 + y2*y2;
    reduce2(sum, sq, sbuf);
    float m = sum / PD;
    float r = rsqrtf(sq / PD - m * m + eps);
    float* o = out + (size_t)row * PD;
    o[t]       = (y0 - m) * r * sc[t]       + bv[t];
    o[t + 256] = (y1 - m) * r * sc[t + 256] + bv[t + 256];
    o[t + 512] = (y2 - m) * r * sc[t + 512] + bv[t + 512];
}

// -------- K10: out=ln(h2+tmp,out_ln,1e-12); src2=src+out; x=ln(src2,n2,1e-5) --
__global__ void k_mid(const float* __restrict__ h2, const float* __restrict__ tp,
                      const float* __restrict__ os, const float* __restrict__ ob,
                      const float* __restrict__ src,
                      const float* __restrict__ n2s, const float* __restrict__ n2b,
                      float* __restrict__ src2, float* __restrict__ xout) {
    __shared__ float sbuf[16];
    int row = blockIdx.x;
    int t = threadIdx.x;
    const float* ap = h2 + (size_t)row * PD;
    const float* bp = tp + (size_t)row * PD;
    float y0 = ap[t] + bp[t];
    float y1 = ap[t + 256] + bp[t + 256];
    float y2 = ap[t + 512] + bp[t + 512];
    float sum = y0 + y1 + y2, sq = y0*y0 + y1*y1 + y2*y2;
    reduce2(sum, sq, sbuf);
    float m = sum / PD;
    float r = rsqrtf(sq / PD - m * m + 1e-12f);
    const float* sp = src + (size_t)row * PD;
    float s0 = sp[t]       + (y0 - m) * r * os[t]       + ob[t];
    float s1 = sp[t + 256] + (y1 - m) * r * os[t + 256] + ob[t + 256];
    float s2 = sp[t + 512] + (y2 - m) * r * os[t + 512] + ob[t + 512];
    float* s2p = src2 + (size_t)row * PD;
    s2p[t] = s0; s2p[t + 256] = s1; s2p[t + 512] = s2;
    sum = s0 + s1 + s2; sq = s0*s0 + s1*s1 + s2*s2;
    reduce2(sum, sq, sbuf);
    m = sum / PD;
    r = rsqrtf(sq / PD - m * m + 1e-5f);
    float* o = xout + (size_t)row * PD;
    o[t]       = (s0 - m) * r * n2s[t]       + n2b[t];
    o[t + 256] = (s1 - m) * r * n2s[t + 256] + n2b[t + 256];
    o[t + 512] = (s2 - m) * r * n2s[t + 512] + n2b[t + 512];
}

// ---------------- SGEMM: C = act((A@B + bias)*scale) (+ residual) -------------
// A: MxK row-major, B: KxN row-major, C: MxN row-major. M%128==0, N%128==0, K%16==0.
// MODE: 0=none, 1=relu, 2=gelu(exact erf)
template<int MODE>
__global__ void __launch_bounds__(256, 2)
k_gemm(const float* __restrict__ A, const float* __restrict__ Bm,
       const float* __restrict__ bias, const float* __restrict__ res,
       float* __restrict__ C, int M, int N, int K, float scale) {
    __shared__ float As[16][128];
    __shared__ float Bs[16][128];
    int tid = threadIdx.x;
    int m0 = blockIdx.y * 128, n0 = blockIdx.x * 128;
    int tm = tid >> 4, tn = tid & 15;
    float acc[8][8];
#pragma unroll
    for (int i = 0; i < 8; i++)
#pragma unroll
        for (int j = 0; j < 8; j++) acc[i][j] = 0.f;

    for (int k0 = 0; k0 < K; k0 += 16) {
#pragma unroll
        for (int i = 0; i < 2; i++) {
            int idx  = tid + i * 256;            // 0..511 (float4 units)
            int arow = idx >> 2, c4 = idx & 3;
            float4 av = *(const float4*)(A + (size_t)(m0 + arow) * K + k0 + c4 * 4);
            As[c4 * 4 + 0][arow] = av.x;
            As[c4 * 4 + 1][arow] = av.y;
            As[c4 * 4 + 2][arow] = av.z;
            As[c4 * 4 + 3][arow] = av.w;
        }
#pragma unroll
        for (int i = 0; i < 2; i++) {
            int idx  = tid + i * 256;
            int brow = idx >> 5, c4 = idx & 31;
            *(float4*)(&Bs[brow][c4 * 4]) =
                *(const float4*)(Bm + (size_t)(k0 + brow) * N + n0 + c4 * 4);
        }
        __syncthreads();
#pragma unroll
        for (int kk = 0; kk < 16; kk++) {
            float ra[8], rb[8];
            *(float4*)(ra)     = *(float4*)(&As[kk][tm * 8]);
            *(float4*)(ra + 4) = *(float4*)(&As[kk][tm * 8 + 4]);
            *(float4*)(rb)     = *(float4*)(&Bs[kk][tn * 8]);
            *(float4*)(rb + 4) = *(float4*)(&Bs[kk][tn * 8 + 4]);
#pragma unroll
            for (int i = 0; i < 8; i++)
#pragma unroll
                for (int j = 0; j < 8; j++)
                    acc[i][j] = fmaf(ra[i], rb[j], acc[i][j]);
        }
        __syncthreads();
    }
#pragma unroll
    for (int i = 0; i < 8; i++) {
        int m = m0 + tm * 8 + i;
        float* crow = C + (size_t)m * N;
        const float* rrow = res ? (res + (size_t)m * N) : nullptr;
#pragma unroll
        for (int j = 0; j < 8; j++) {
            int n = n0 + tn * 8 + j;
            float v = (acc[i][j] + bias[n]) * scale;
            if (MODE == 1) v = fmaxf(v, 0.f);
            if (MODE == 2) v = 0.5f * v * (1.f + erff(v * 0.7071067811865476f));
            if (rrow) v += rrow[n];
            crow[n] = v;
        }
    }
}

// ---------------- banded attention (flash-style, window W=256) ----------------
// Q,K,V,O layout: [B*S, H*HD] row-major. Q already scaled by 1/sqrt(HD).
// Block: 128 queries (x=qblk in {0,1}, y=chunk 0..31, z = b*H+h). 128 threads.
__global__ void __launch_bounds__(128)
k_attn(const float* __restrict__ Q, const float* __restrict__ Kt,
       const float* __restrict__ V, float* __restrict__ O) {
    extern __shared__ float sm[];
    float* Ks = sm;            // 64*64
    float* Vs = sm + 4096;     // 64*64
    float* Sc = sm + 8192;     // 128*65
    int tid  = threadIdx.x;
    int qblk = blockIdx.x;
    int c    = blockIdx.y;
    int bh   = blockIdx.z;
    int b = bh / PH, hh = bh % PH;
    int qbase = c * PW + qblk * 128;
    int qpos  = qbase + tid;

    const float* qp = Q + ((size_t)(b * PS + qpos)) * PD + hh * PHD;
    float q[64];
#pragma unroll
    for (int d = 0; d < 64; d += 4) {
        float4 tv = *(const float4*)(qp + d);
        q[d] = tv.x; q[d + 1] = tv.y; q[d + 2] = tv.z; q[d + 3] = tv.w;
    }
    float acc[64];
#pragma unroll
    for (int d = 0; d < 64; d++) acc[d] = 0.f;
    float mrun = -1e30f, lrun = 0.f;

    for (int t = 0; t < 12; t++) {
        int tb = c * PW - PW + t * 64;
        if (tb + 63 < qbase - PW || tb > qbase + 127 + PW) continue;  // outside band
        if (tb + 63 < 0 || tb >= PS) continue;                        // outside sequence
        // stage K,V tile (64 keys x 64 dims)
#pragma unroll
        for (int i = 0; i < 8; i++) {
            int idx = tid + i * 128;         // float4 index 0..1023
            int r = idx >> 4, c4 = idx & 15;
            int kp = tb + r;
            float4 kv = make_float4(0.f, 0.f, 0.f, 0.f), vv = kv;
            if (kp >= 0 && kp < PS) {
                size_t off = ((size_t)(b * PS + kp)) * PD + hh * PHD + c4 * 4;
                kv = *(const float4*)(Kt + off);
                vv = *(const float4*)(V + off);
            }
            *(float4*)(&Ks[r * 64 + c4 * 4]) = kv;
            *(float4*)(&Vs[r * 64 + c4 * 4]) = vv;
        }
        __syncthreads();

        float tmax = -1e30f;
        for (int j = 0; j < 64; j++) {
            int kp = tb + j;
            int dd = kp - qpos;
            float s = -1e30f;
            if (kp >= 0 && kp < PS && dd <= PW && dd >= -PW) {
                s = 0.f;
                const float4* kr = (const float4*)(Ks + j * 64);
#pragma unroll
                for (int d4 = 0; d4 < 16; d4++) {
                    float4 kv = kr[d4];
                    s = fmaf(q[d4 * 4 + 0], kv.x, s);
                    s = fmaf(q[d4 * 4 + 1], kv.y, s);
                    s = fmaf(q[d4 * 4 + 2], kv.z, s);
                    s = fmaf(q[d4 * 4 + 3], kv.w, s);
                }
            }
            Sc[tid * 65 + j] = s;
            tmax = fmaxf(tmax, s);
        }
        if (tmax > -1e29f) {
            float mnew = fmaxf(mrun, tmax);
            float corr = __expf(mrun - mnew);
            lrun *= corr;
#pragma unroll
            for (int d = 0; d < 64; d++) acc[d] *= corr;
            for (int j = 0; j < 64; j++) {
                float s = Sc[tid * 65 + j];
                if (s > -1e29f) {
                    float p = __expf(s - mnew);
                    lrun += p;
                    const float4* vr = (const float4*)(Vs + j * 64);
#pragma unroll
                    for (int d4 = 0; d4 < 16; d4++) {
                        float4 vv = vr[d4];
                        acc[d4 * 4 + 0] = fmaf(p, vv.x, acc[d4 * 4 + 0]);
                        acc[d4 * 4 + 1] = fmaf(p, vv.y, acc[d4 * 4 + 1]);
                        acc[d4 * 4 + 2] = fmaf(p, vv.z, acc[d4 * 4 + 2]);
                        acc[d4 * 4 + 3] = fmaf(p, vv.w, acc[d4 * 4 + 3]);
                    }
                }
            }
            mrun = mnew;
        }
        __syncthreads();
    }
    float inv = 1.f / lrun;
    float* op = O + ((size_t)(b * PS + qpos)) * PD + hh * PHD;
#pragma unroll
    for (int d = 0; d < 64; d += 4) {
        float4 ov;
        ov.x = acc[d] * inv; ov.y = acc[d + 1] * inv;
        ov.z = acc[d + 2] * inv; ov.w = acc[d + 3] * inv;
        *(float4*)(op + d) = ov;
    }
}

// ------------------------------- launch ---------------------------------------
extern "C" void kernel_launch(void* const* d_in, const int* in_sizes, int n_in,
                              void* d_out, int out_size) {
    const float* src   = (const float*)d_in[0];
    const float* pos   = (const float*)d_in[1];
    const float* tt    = (const float*)d_in[2];
    const float* embs  = (const float*)d_in[3];
    const float* embb  = (const float*)d_in[4];
    const float* wq    = (const float*)d_in[5];
    const float* bq    = (const float*)d_in[6];
    const float* wk    = (const float*)d_in[7];
    const float* bk    = (const float*)d_in[8];
    const float* wv    = (const float*)d_in[9];
    const float* bv    = (const float*)d_in[10];
    const float* wo    = (const float*)d_in[11];
    const float* bo    = (const float*)d_in[12];
    const float* atts  = (const float*)d_in[13];
    const float* attb  = (const float*)d_in[14];
    const float* wi    = (const float*)d_in[15];
    const float* bi    = (const float*)d_in[16];
    const float* wo2   = (const float*)d_in[17];
    const float* bo2   = (const float*)d_in[18];
    const float* outs  = (const float*)d_in[19];
    const float* outb  = (const float*)d_in[20];
    const float* n1s   = (const float*)d_in[21];
    const float* n1b   = (const float*)d_in[22];
    const float* n2s   = (const float*)d_in[23];
    const float* n2b   = (const float*)d_in[24];
    const float* w1    = (const float*)d_in[25];
    const float* b1    = (const float*)d_in[26];
    const float* w2    = (const float*)d_in[27];
    const float* b2    = (const float*)d_in[28];
    float* out = (float*)d_out;

    float *p_h, *p_h2, *p_q, *p_k, *p_v, *p_a, *p_ff;
    cudaGetSymbolAddress((void**)&p_h,  g_h);
    cudaGetSymbolAddress((void**)&p_h2, g_h2);
    cudaGetSymbolAddress((void**)&p_q,  g_q);
    cudaGetSymbolAddress((void**)&p_k,  g_k);
    cudaGetSymbolAddress((void**)&p_v,  g_v);
    cudaGetSymbolAddress((void**)&p_a,  g_a);
    cudaGetSymbolAddress((void**)&p_ff, g_ff);
    float* p_tmp  = p_q;   // reuse after attention
    float* p_src2 = p_k;   // reuse after attention

    int attn_smem = (4096 + 4096 + 128 * 65) * (int)sizeof(float);
    cudaFuncSetAttribute(k_attn, cudaFuncAttributeMaxDynamicSharedMemorySize, attn_smem);

    dim3 gD(PD / 128, NT / 128);     // N=768
    dim3 gF(PDFF / 128, NT / 128);   // N=3072

    // 1. embed: double LN
    k_embed<<<NT, 256>>>(src, pos, tt, n1s, n1b, embs, embb, p_h);
    // 2-4. QKV projections (q scaled by 1/8)
    k_gemm<0><<<gD, 256>>>(p_h, wq, bq, nullptr, p_q, NT, PD, PD, 0.125f);
    k_gemm<0><<<gD, 256>>>(p_h, wk, bk, nullptr, p_k, NT, PD, PD, 1.f);
    k_gemm<0><<<gD, 256>>>(p_h, wv, bv, nullptr, p_v, NT, PD, PD, 1.f);
    // 5. banded attention
    k_attn<<<dim3(2, PS / PW, PB * PH), 128, attn_smem>>>(p_q, p_k, p_v, p_a);
    // 6. attn out proj
    k_gemm<0><<<gD, 256>>>(p_a, wo, bo, nullptr, p_tmp, NT, PD, PD, 1.f);
    // 7. h2 = ln(h + proj, attn_ln, 1e-12)
    k_add_ln<<<NT, 256>>>(p_h, p_tmp, atts, attb, 1e-12f, p_h2);
    // 8. FFN1 + exact GELU
    k_gemm<2><<<gF, 256>>>(p_h2, wi, bi, nullptr, p_ff, NT, PDFF, PD, 1.f);
    // 9. FFN2
    k_gemm<0><<<gD, 256>>>(p_ff, wo2, bo2, nullptr, p_tmp, NT, PD, PDFF, 1.f);
    // 10. out-LN -> src2 -> n2-LN (x into p_h, reused)
    k_mid<<<NT, 256>>>(p_h2, p_tmp, outs, outb, src, n2s, n2b, p_src2, p_h);
    // 11. MLP1 + ReLU
    k_gemm<1><<<gF, 256>>>(p_h, w1, b1, nullptr, p_ff, NT, PDFF, PD, 1.f);
    // 12. MLP2 + residual(src2) -> d_out
    k_gemm<0><<<gD, 256>>>(p_ff, w2, b2, p_src2, out, NT, PD, PDFF, 1.f);
}

// round 4
// speedup vs baseline: 2.0980x; 2.0980x over previous
#include <cuda_runtime.h>
#include <cuda_bf16.h>
#include <math.h>
#include <stdint.h>

static constexpr int PB  = 2;
static constexpr int PS  = 8192;
static constexpr int PD  = 768;
static constexpr int PH  = 12;
static constexpr int PHD = 64;
static constexpr int PW  = 256;
static constexpr int PDFF= 3072;
static constexpr int NT  = PB * PS;     // 16384

// ---------------- scratch (device globals; no allocation) ---------------------
__device__ float g_h   [NT * PD];
__device__ float g_q   [NT * PD];
__device__ float g_k   [NT * PD];
__device__ float g_v   [NT * PD];
__device__ float g_tmp [NT * PD];
__device__ float g_h2  [NT * PD];
__device__ float g_src2[NT * PD];

__device__ __nv_bfloat16 g_hh [NT * PD], g_hl [NT * PD];
__device__ __nv_bfloat16 g_h2h[NT * PD], g_h2l[NT * PD];
__device__ __nv_bfloat16 g_aah[NT * PD], g_aal[NT * PD];
__device__ __nv_bfloat16 g_xh [NT * PD], g_xl [NT * PD];
__device__ __nv_bfloat16 g_ffh[(size_t)NT * PDFF], g_ffl[(size_t)NT * PDFF];

// weights, converted to bf16 hi/lo and TRANSPOSED to [N,K]
__device__ __nv_bfloat16 g_wqh [PD * PD],  g_wql [PD * PD];
__device__ __nv_bfloat16 g_wkh [PD * PD],  g_wkl [PD * PD];
__device__ __nv_bfloat16 g_wvh [PD * PD],  g_wvl [PD * PD];
__device__ __nv_bfloat16 g_woh [PD * PD],  g_wol [PD * PD];
__device__ __nv_bfloat16 g_wih [PDFF * PD], g_wil [PDFF * PD];
__device__ __nv_bfloat16 g_wo2h[PD * PDFF], g_wo2l[PD * PDFF];
__device__ __nv_bfloat16 g_w1h [PDFF * PD], g_w1l [PDFF * PD];
__device__ __nv_bfloat16 g_w2h [PD * PDFF], g_w2l [PD * PDFF];

// ---------------- helpers -----------------------------------------------------
__device__ __forceinline__ uint32_t smem_u32(const void* p) {
    uint32_t a;
    asm("{ .reg .u64 t; cvta.to.shared.u64 t, %1; cvt.u32.u64 %0, t; }"
        : "=r"(a) : "l"(p));
    return a;
}
__device__ __forceinline__ void cp16(uint32_t saddr, const void* gaddr) {
    asm volatile("cp.async.cg.shared.global [%0], [%1], 16;"
                 :: "r"(saddr), "l"(gaddr) : "memory");
}
#define CP_COMMIT() asm volatile("cp.async.commit_group;" ::: "memory")
#define CP_WAIT(n)  asm volatile("cp.async.wait_group %0;" :: "n"(n) : "memory")

__device__ __forceinline__ void ldsm4(uint32_t* r, uint32_t addr) {
    asm volatile("ldmatrix.sync.aligned.m8n8.x4.shared.b16 {%0,%1,%2,%3}, [%4];"
                 : "=r"(r[0]), "=r"(r[1]), "=r"(r[2]), "=r"(r[3]) : "r"(addr));
}
__device__ __forceinline__ void ldsm2(uint32_t* r, uint32_t addr) {
    asm volatile("ldmatrix.sync.aligned.m8n8.x2.shared.b16 {%0,%1}, [%2];"
                 : "=r"(r[0]), "=r"(r[1]) : "r"(addr));
}
__device__ __forceinline__ void mma16816(float* c, const uint32_t* a, const uint32_t* b) {
    asm volatile(
        "mma.sync.aligned.m16n8k16.row.col.f32.bf16.bf16.f32 "
        "{%0,%1,%2,%3}, {%4,%5,%6,%7}, {%8,%9}, {%0,%1,%2,%3};"
        : "+f"(c[0]), "+f"(c[1]), "+f"(c[2]), "+f"(c[3])
        : "r"(a[0]), "r"(a[1]), "r"(a[2]), "r"(a[3]), "r"(b[0]), "r"(b[1]));
}
__device__ __forceinline__ void bf16split(float v, __nv_bfloat16& h, __nv_bfloat16& l) {
    h = __float2bfloat16(v);
    l = __float2bfloat16(v - __bfloat162float(h));
}

// ---------------- block reduce (sum of two values, 256 threads) ---------------
__device__ __forceinline__ void reduce2(float& a, float& b, float* sbuf) {
    int lane = threadIdx.x & 31;
    int wid  = threadIdx.x >> 5;
#pragma unroll
    for (int o = 16; o > 0; o >>= 1) {
        a += __shfl_down_sync(0xffffffffu, a, o);
        b += __shfl_down_sync(0xffffffffu, b, o);
    }
    __syncthreads();
    if (lane == 0) { sbuf[wid] = a; sbuf[8 + wid] = b; }
    __syncthreads();
    if (threadIdx.x < 32) {
        a = (lane < 8) ? sbuf[lane] : 0.f;
        b = (lane < 8) ? sbuf[8 + lane] : 0.f;
#pragma unroll
        for (int o = 4; o > 0; o >>= 1) {
            a += __shfl_down_sync(0xffffffffu, a, o);
            b += __shfl_down_sync(0xffffffffu, b, o);
        }
        if (lane == 0) { sbuf[0] = a; sbuf[8] = b; }
    }
    __syncthreads();
    a = sbuf[0]; b = sbuf[8];
}

// -------- weight convert + transpose: W[K,N] fp32 -> T[N,K] bf16 hi/lo --------
__global__ void k_wconv(const float* __restrict__ W, __nv_bfloat16* __restrict__ Th,
                        __nv_bfloat16* __restrict__ Tl, int K, int N) {
    __shared__ float t[32][33];
    int n0 = blockIdx.x * 32, k0 = blockIdx.y * 32;
    int tx = threadIdx.x, ty = threadIdx.y;   // 32 x 8
#pragma unroll
    for (int i = 0; i < 32; i += 8)
        t[ty + i][tx] = W[(size_t)(k0 + ty + i) * N + n0 + tx];
    __syncthreads();
#pragma unroll
    for (int i = 0; i < 32; i += 8) {
        float v = t[tx][ty + i];
        __nv_bfloat16 h, l; bf16split(v, h, l);
        size_t o = (size_t)(n0 + ty + i) * K + k0 + tx;
        Th[o] = h; Tl[o] = l;
    }
}

// -------- K1: double LN + pos/tt; writes h fp32 + bf16 hi/lo ------------------
__global__ void k_embed(const float* __restrict__ src, const float* __restrict__ pos,
                        const float* __restrict__ tt,
                        const float* __restrict__ n1s, const float* __restrict__ n1b,
                        const float* __restrict__ es,  const float* __restrict__ eb,
                        float* __restrict__ out,
                        __nv_bfloat16* __restrict__ oh, __nv_bfloat16* __restrict__ ol) {
    __shared__ float sbuf[16];
    int row = blockIdx.x;
    int s   = row % PS;
    const float* x = src + (size_t)row * PD;
    int t = threadIdx.x;
    float v0 = x[t], v1 = x[t + 256], v2 = x[t + 512];
    float sum = v0 + v1 + v2, sq = v0*v0 + v1*v1 + v2*v2;
    reduce2(sum, sq, sbuf);
    float m = sum / PD;
    float r = rsqrtf(sq / PD - m * m + 1e-5f);
    const float* ps = pos + (size_t)s * PD;
    float y0 = (v0 - m) * r * n1s[t]       + n1b[t]       + ps[t]       + tt[t];
    float y1 = (v1 - m) * r * n1s[t + 256] + n1b[t + 256] + ps[t + 256] + tt[t + 256];
    float y2 = (v2 - m) * r * n1s[t + 512] + n1b[t + 512] + ps[t + 512] + tt[t + 512];
    sum = y0 + y1 + y2; sq = y0*y0 + y1*y1 + y2*y2;
    reduce2(sum, sq, sbuf);
    m = sum / PD;
    r = rsqrtf(sq / PD - m * m + 1e-12f);
    size_t base = (size_t)row * PD;
    float z0 = (y0 - m) * r * es[t]       + eb[t];
    float z1 = (y1 - m) * r * es[t + 256] + eb[t + 256];
    float z2 = (y2 - m) * r * es[t + 512] + eb[t + 512];
    out[base + t] = z0; out[base + t + 256] = z1; out[base + t + 512] = z2;
    __nv_bfloat16 h, l;
    bf16split(z0, h, l); oh[base + t]       = h; ol[base + t]       = l;
    bf16split(z1, h, l); oh[base + t + 256] = h; ol[base + t + 256] = l;
    bf16split(z2, h, l); oh[base + t + 512] = h; ol[base + t + 512] = l;
}

// -------- out = ln(a + b); writes fp32 + bf16 hi/lo ---------------------------
__global__ void k_add_ln(const float* __restrict__ a, const float* __restrict__ b,
                         const float* __restrict__ sc, const float* __restrict__ bv,
                         float eps, float* __restrict__ out,
                         __nv_bfloat16* __restrict__ oh, __nv_bfloat16* __restrict__ ol) {
    __shared__ float sbuf[16];
    int row = blockIdx.x;
    int t = threadIdx.x;
    const float* ap = a + (size_t)row * PD;
    const float* bp = b + (size_t)row * PD;
    float y0 = ap[t] + bp[t];
    float y1 = ap[t + 256] + bp[t + 256];
    float y2 = ap[t + 512] + bp[t + 512];
    float sum = y0 + y1 + y2, sq = y0*y0 + y1*y1 + y2*y2;
    reduce2(sum, sq, sbuf);
    float m = sum / PD;
    float r = rsqrtf(sq / PD - m * m + eps);
    size_t base = (size_t)row * PD;
    float z0 = (y0 - m) * r * sc[t]       + bv[t];
    float z1 = (y1 - m) * r * sc[t + 256] + bv[t + 256];
    float z2 = (y2 - m) * r * sc[t + 512] + bv[t + 512];
    out[base + t] = z0; out[base + t + 256] = z1; out[base + t + 512] = z2;
    __nv_bfloat16 h, l;
    bf16split(z0, h, l); oh[base + t]       = h; ol[base + t]       = l;
    bf16split(z1, h, l); oh[base + t + 256] = h; ol[base + t + 256] = l;
    bf16split(z2, h, l); oh[base + t + 512] = h; ol[base + t + 512] = l;
}

// -------- out-LN -> src2 (fp32) -> n2-LN -> x (bf16 hi/lo) --------------------
__global__ void k_mid(const float* __restrict__ h2, const float* __restrict__ tp,
                      const float* __restrict__ os, const float* __restrict__ ob,
                      const float* __restrict__ src,
                      const float* __restrict__ n2s, const float* __restrict__ n2b,
                      float* __restrict__ src2,
                      __nv_bfloat16* __restrict__ xh, __nv_bfloat16* __restrict__ xl) {
    __shared__ float sbuf[16];
    int row = blockIdx.x;
    int t = threadIdx.x;
    const float* ap = h2 + (size_t)row * PD;
    const float* bp = tp + (size_t)row * PD;
    float y0 = ap[t] + bp[t];
    float y1 = ap[t + 256] + bp[t + 256];
    float y2 = ap[t + 512] + bp[t + 512];
    float sum = y0 + y1 + y2, sq = y0*y0 + y1*y1 + y2*y2;
    reduce2(sum, sq, sbuf);
    float m = sum / PD;
    float r = rsqrtf(sq / PD - m * m + 1e-12f);
    const float* sp = src + (size_t)row * PD;
    float s0 = sp[t]       + (y0 - m) * r * os[t]       + ob[t];
    float s1 = sp[t + 256] + (y1 - m) * r * os[t + 256] + ob[t + 256];
    float s2 = sp[t + 512] + (y2 - m) * r * os[t + 512] + ob[t + 512];
    size_t base = (size_t)row * PD;
    src2[base + t] = s0; src2[base + t + 256] = s1; src2[base + t + 512] = s2;
    sum = s0 + s1 + s2; sq = s0*s0 + s1*s1 + s2*s2;
    reduce2(sum, sq, sbuf);
    m = sum / PD;
    r = rsqrtf(sq / PD - m * m + 1e-5f);
    float z0 = (s0 - m) * r * n2s[t]       + n2b[t];
    float z1 = (s1 - m) * r * n2s[t + 256] + n2b[t + 256];
    float z2 = (s2 - m) * r * n2s[t + 512] + n2b[t + 512];
    __nv_bfloat16 h, l;
    bf16split(z0, h, l); xh[base + t]       = h; xl[base + t]       = l;
    bf16split(z1, h, l); xh[base + t + 256] = h; xl[base + t + 256] = l;
    bf16split(z2, h, l); xh[base + t + 512] = h; xl[base + t + 512] = l;
}

// ---------------- HMMA GEMM: C = act((A@B^T + bias)*scale) (+res) -------------
// A: [M,K] bf16 hi/lo. B: [N,K] bf16 hi/lo. 3-pass split AhBh+AhBl+AlBh.
// Tile 128x128x64, 8 warps (2m x 4n), warp tile 64x32, cp.async double buffer.
static constexpr int LDT   = 72;                // padded row stride (bf16 elems)
static constexpr int ABYTES= 128 * LDT * 2;     // 18432 per array
static constexpr int STAGE = 4 * ABYTES;        // 73728
static constexpr int GSMEM = 2 * STAGE;         // 147456

template<int MODE, bool WF32, bool WBF16, bool HASRES>
__global__ void __launch_bounds__(256, 1)
k_mma_gemm(const __nv_bfloat16* __restrict__ Ah, const __nv_bfloat16* __restrict__ Al,
           const __nv_bfloat16* __restrict__ Bh, const __nv_bfloat16* __restrict__ Bl,
           const float* __restrict__ bias, const float* __restrict__ res,
           float* __restrict__ Cf, __nv_bfloat16* __restrict__ Ch,
           __nv_bfloat16* __restrict__ Cl, int M, int N, int K, float scale) {
    extern __shared__ char smem[];
    uint32_t sbase = smem_u32(smem);
    int tid  = threadIdx.x;
    int wid  = tid >> 5, lane = tid & 31;
    int wm   = (wid >> 2) * 64;     // warp m offset (0 / 64)
    int wn   = (wid & 3) * 32;      // warp n offset

    int m0 = blockIdx.y * 128, n0 = blockIdx.x * 128;
    int nK = K >> 6;

    const __nv_bfloat16* pa0 = Ah + (size_t)m0 * K;
    const __nv_bfloat16* pa1 = Al + (size_t)m0 * K;
    const __nv_bfloat16* pb0 = Bh + (size_t)n0 * K;
    const __nv_bfloat16* pb1 = Bl + (size_t)n0 * K;

    float acc[4][4][4];
#pragma unroll
    for (int a = 0; a < 4; a++)
#pragma unroll
        for (int b = 0; b < 4; b++)
#pragma unroll
            for (int c = 0; c < 4; c++) acc[a][b][c] = 0.f;

    // per-thread load mapping: 1024 16B-transfers per array per stage
    int lrow = tid >> 3;            // base row (0..31), +32*i
    int lseg = tid & 7;             // 16B segment within 128B row

    auto load_stage = [&](int kc, int s) {
        uint32_t st = sbase + s * STAGE;
        size_t ko = (size_t)(kc << 6) + (size_t)lseg * 8;
#pragma unroll
        for (int i = 0; i < 4; i++) {
            int r = lrow + i * 32;
            uint32_t so = (uint32_t)r * (LDT * 2) + (uint32_t)lseg * 16;
            size_t go = (size_t)r * K + ko;
            cp16(st + so,              pa0 + go);
            cp16(st + ABYTES + so,     pa1 + go);
            cp16(st + 2 * ABYTES + so, pb0 + go);
            cp16(st + 3 * ABYTES + so, pb1 + go);
        }
    };

    load_stage(0, 0);
    CP_COMMIT();

    // ldmatrix address components
    int a_r  = lane & 15;           // row within 16-row A tile
    int a_k8 = (lane >> 4) * 8;     // k offset 0/8
    int b_r  = lane & 7;            // row within 8-row B tile
    int b_k8 = ((lane >> 3) & 1) * 8;

    for (int kc = 0; kc < nK; kc++) {
        int s = kc & 1;
        if (kc + 1 < nK) {
            load_stage(kc + 1, s ^ 1);
            CP_COMMIT();
            CP_WAIT(1);
        } else {
            CP_WAIT(0);
        }
        __syncthreads();

        uint32_t sA = sbase + s * STAGE;
        uint32_t sB = sA + 2 * ABYTES;
#pragma unroll
        for (int ks = 0; ks < 4; ks++) {
            uint32_t ah[4][4], al[4][4], bh[4][2], bl[4][2];
#pragma unroll
            for (int mi = 0; mi < 4; mi++) {
                uint32_t off = ((uint32_t)(wm + mi * 16 + a_r) * LDT +
                                (uint32_t)(ks * 16 + a_k8)) * 2;
                ldsm4(ah[mi], sA + off);
                ldsm4(al[mi], sA + ABYTES + off);
            }
#pragma unroll
            for (int ni = 0; ni < 4; ni++) {
                uint32_t off = ((uint32_t)(wn + ni * 8 + b_r) * LDT +
                                (uint32_t)(ks * 16 + b_k8)) * 2;
                ldsm2(bh[ni], sB + off);
                ldsm2(bl[ni], sB + ABYTES + off);
            }
#pragma unroll
            for (int mi = 0; mi < 4; mi++)
#pragma unroll
                for (int ni = 0; ni < 4; ni++) {
                    mma16816(acc[mi][ni], ah[mi], bh[ni]);
                    mma16816(acc[mi][ni], ah[mi], bl[ni]);
                    mma16816(acc[mi][ni], al[mi], bh[ni]);
                }
        }
        __syncthreads();
    }

    // -------- epilogue: registers -> global -----------------------------------
    auto epi = [&](float v0, float v1, int m, int n) {
        float2 bb = *(const float2*)(bias + n);
        float o0 = (v0 + bb.x) * scale;
        float o1 = (v1 + bb.y) * scale;
        if (MODE == 1) { o0 = fmaxf(o0, 0.f); o1 = fmaxf(o1, 0.f); }
        if (MODE == 2) {
            o0 = 0.5f * o0 * (1.f + erff(o0 * 0.7071067811865476f));
            o1 = 0.5f * o1 * (1.f + erff(o1 * 0.7071067811865476f));
        }
        size_t off = (size_t)m * N + n;
        if (HASRES) {
            float2 rr = *(const float2*)(res + off);
            o0 += rr.x; o1 += rr.y;
        }
        if (WF32) {
            float2 ov = { o0, o1 };
            *(float2*)(Cf + off) = ov;
        }
        if (WBF16) {
            __nv_bfloat16 h0, l0, h1, l1;
            bf16split(o0, h0, l0); bf16split(o1, h1, l1);
            __nv_bfloat162 ph; ph.x = h0; ph.y = h1;
            __nv_bfloat162 pl; pl.x = l0; pl.y = l1;
            *(__nv_bfloat162*)(Ch + off) = ph;
            *(__nv_bfloat162*)(Cl + off) = pl;
        }
    };
    int mrow = lane >> 2;
    int ncol = (lane & 3) * 2;
#pragma unroll
    for (int mi = 0; mi < 4; mi++)
#pragma unroll
        for (int ni = 0; ni < 4; ni++) {
            int m = m0 + wm + mi * 16 + mrow;
            int n = n0 + wn + ni * 8 + ncol;
            epi(acc[mi][ni][0], acc[mi][ni][1], m,     n);
            epi(acc[mi][ni][2], acc[mi][ni][3], m + 8, n);
        }
}

// ---------------- banded attention (flash-style, fp32; bf16 hi/lo out) --------
__global__ void __launch_bounds__(128)
k_attn(const float* __restrict__ Q, const float* __restrict__ Kt,
       const float* __restrict__ V,
       __nv_bfloat16* __restrict__ Oh, __nv_bfloat16* __restrict__ Ol) {
    extern __shared__ float sm[];
    float* Ks = sm;            // 64*64
    float* Vs = sm + 4096;     // 64*64
    float* Sc = sm + 8192;     // 128*65
    int tid  = threadIdx.x;
    int qblk = blockIdx.x;
    int c    = blockIdx.y;
    int bh   = blockIdx.z;
    int b = bh / PH, hh = bh % PH;
    int qbase = c * PW + qblk * 128;
    int qpos  = qbase + tid;

    const float* qp = Q + ((size_t)(b * PS + qpos)) * PD + hh * PHD;
    float q[64];
#pragma unroll
    for (int d = 0; d < 64; d += 4) {
        float4 tv = *(const float4*)(qp + d);
        q[d] = tv.x; q[d + 1] = tv.y; q[d + 2] = tv.z; q[d + 3] = tv.w;
    }
    float acc[64];
#pragma unroll
    for (int d = 0; d < 64; d++) acc[d] = 0.f;
    float mrun = -1e30f, lrun = 0.f;

    for (int t = 0; t < 12; t++) {
        int tb = c * PW - PW + t * 64;
        if (tb + 63 < qbase - PW || tb > qbase + 127 + PW) continue;
        if (tb + 63 < 0 || tb >= PS) continue;
#pragma unroll
        for (int i = 0; i < 8; i++) {
            int idx = tid + i * 128;
            int r = idx >> 4, c4 = idx & 15;
            int kp = tb + r;
            float4 kv = make_float4(0.f, 0.f, 0.f, 0.f), vv = kv;
            if (kp >= 0 && kp < PS) {
                size_t off = ((size_t)(b * PS + kp)) * PD + hh * PHD + c4 * 4;
                kv = *(const float4*)(Kt + off);
                vv = *(const float4*)(V + off);
            }
            *(float4*)(&Ks[r * 64 + c4 * 4]) = kv;
            *(float4*)(&Vs[r * 64 + c4 * 4]) = vv;
        }
        __syncthreads();

        float tmax = -1e30f;
        for (int j = 0; j < 64; j++) {
            int kp = tb + j;
            int dd = kp - qpos;
            float s = -1e30f;
            if (kp >= 0 && kp < PS && dd <= PW && dd >= -PW) {
                s = 0.f;
                const float4* kr = (const float4*)(Ks + j * 64);
#pragma unroll
                for (int d4 = 0; d4 < 16; d4++) {
                    float4 kv = kr[d4];
                    s = fmaf(q[d4 * 4 + 0], kv.x, s);
                    s = fmaf(q[d4 * 4 + 1], kv.y, s);
                    s = fmaf(q[d4 * 4 + 2], kv.z, s);
                    s = fmaf(q[d4 * 4 + 3], kv.w, s);
                }
            }
            Sc[tid * 65 + j] = s;
            tmax = fmaxf(tmax, s);
        }
        if (tmax > -1e29f) {
            float mnew = fmaxf(mrun, tmax);
            float corr = __expf(mrun - mnew);
            lrun *= corr;
#pragma unroll
            for (int d = 0; d < 64; d++) acc[d] *= corr;
            for (int j = 0; j < 64; j++) {
                float s = Sc[tid * 65 + j];
                if (s > -1e29f) {
                    float p = __expf(s - mnew);
                    lrun += p;
                    const float4* vr = (const float4*)(Vs + j * 64);
#pragma unroll
                    for (int d4 = 0; d4 < 16; d4++) {
                        float4 vv = vr[d4];
                        acc[d4 * 4 + 0] = fmaf(p, vv.x, acc[d4 * 4 + 0]);
                        acc[d4 * 4 + 1] = fmaf(p, vv.y, acc[d4 * 4 + 1]);
                        acc[d4 * 4 + 2] = fmaf(p, vv.z, acc[d4 * 4 + 2]);
                        acc[d4 * 4 + 3] = fmaf(p, vv.w, acc[d4 * 4 + 3]);
                    }
                }
            }
            mrun = mnew;
        }
        __syncthreads();
    }
    float inv = 1.f / lrun;
    size_t ob = ((size_t)(b * PS + qpos)) * PD + hh * PHD;
#pragma unroll
    for (int d = 0; d < 64; d += 2) {
        float v0 = acc[d] * inv, v1 = acc[d + 1] * inv;
        __nv_bfloat16 h0, l0, h1, l1;
        bf16split(v0, h0, l0); bf16split(v1, h1, l1);
        __nv_bfloat162 ph; ph.x = h0; ph.y = h1;
        __nv_bfloat162 pl; pl.x = l0; pl.y = l1;
        *(__nv_bfloat162*)(Oh + ob + d) = ph;
        *(__nv_bfloat162*)(Ol + ob + d) = pl;
    }
}

// ------------------------------- launch ---------------------------------------
extern "C" void kernel_launch(void* const* d_in, const int* in_sizes, int n_in,
                              void* d_out, int out_size) {
    const float* src   = (const float*)d_in[0];
    const float* pos   = (const float*)d_in[1];
    const float* tt    = (const float*)d_in[2];
    const float* embs  = (const float*)d_in[3];
    const float* embb  = (const float*)d_in[4];
    const float* wq    = (const float*)d_in[5];
    const float* bq    = (const float*)d_in[6];
    const float* wk    = (const float*)d_in[7];
    const float* bk    = (const float*)d_in[8];
    const float* wv    = (const float*)d_in[9];
    const float* bv    = (const float*)d_in[10];
    const float* wo    = (const float*)d_in[11];
    const float* bo    = (const float*)d_in[12];
    const float* atts  = (const float*)d_in[13];
    const float* attb  = (const float*)d_in[14];
    const float* wi    = (const float*)d_in[15];
    const float* bi    = (const float*)d_in[16];
    const float* wo2   = (const float*)d_in[17];
    const float* bo2   = (const float*)d_in[18];
    const float* outs  = (const float*)d_in[19];
    const float* outb  = (const float*)d_in[20];
    const float* n1s   = (const float*)d_in[21];
    const float* n1b   = (const float*)d_in[22];
    const float* n2s   = (const float*)d_in[23];
    const float* n2b   = (const float*)d_in[24];
    const float* w1    = (const float*)d_in[25];
    const float* b1    = (const float*)d_in[26];
    const float* w2    = (const float*)d_in[27];
    const float* b2    = (const float*)d_in[28];
    float* out = (float*)d_out;

    float *p_h, *p_q, *p_k, *p_v, *p_tmp, *p_h2, *p_src2;
    cudaGetSymbolAddress((void**)&p_h,    g_h);
    cudaGetSymbolAddress((void**)&p_q,    g_q);
    cudaGetSymbolAddress((void**)&p_k,    g_k);
    cudaGetSymbolAddress((void**)&p_v,    g_v);
    cudaGetSymbolAddress((void**)&p_tmp,  g_tmp);
    cudaGetSymbolAddress((void**)&p_h2,   g_h2);
    cudaGetSymbolAddress((void**)&p_src2, g_src2);

    __nv_bfloat16 *hh, *hl, *h2h, *h2l, *aah, *aal, *xh, *xl, *ffh, *ffl;
    cudaGetSymbolAddress((void**)&hh,  g_hh);   cudaGetSymbolAddress((void**)&hl,  g_hl);
    cudaGetSymbolAddress((void**)&h2h, g_h2h);  cudaGetSymbolAddress((void**)&h2l, g_h2l);
    cudaGetSymbolAddress((void**)&aah, g_aah);  cudaGetSymbolAddress((void**)&aal, g_aal);
    cudaGetSymbolAddress((void**)&xh,  g_xh);   cudaGetSymbolAddress((void**)&xl,  g_xl);
    cudaGetSymbolAddress((void**)&ffh, g_ffh);  cudaGetSymbolAddress((void**)&ffl, g_ffl);

    __nv_bfloat16 *wqh, *wql, *wkh, *wkl, *wvh, *wvl, *woh, *wol;
    __nv_bfloat16 *wih, *wil, *wo2h, *wo2l, *w1h, *w1l, *w2h, *w2l;
    cudaGetSymbolAddress((void**)&wqh,  g_wqh);  cudaGetSymbolAddress((void**)&wql,  g_wql);
    cudaGetSymbolAddress((void**)&wkh,  g_wkh);  cudaGetSymbolAddress((void**)&wkl,  g_wkl);
    cudaGetSymbolAddress((void**)&wvh,  g_wvh);  cudaGetSymbolAddress((void**)&wvl,  g_wvl);
    cudaGetSymbolAddress((void**)&woh,  g_woh);  cudaGetSymbolAddress((void**)&wol,  g_wol);
    cudaGetSymbolAddress((void**)&wih,  g_wih);  cudaGetSymbolAddress((void**)&wil,  g_wil);
    cudaGetSymbolAddress((void**)&wo2h, g_wo2h); cudaGetSymbolAddress((void**)&wo2l, g_wo2l);
    cudaGetSymbolAddress((void**)&w1h,  g_w1h);  cudaGetSymbolAddress((void**)&w1l,  g_w1l);
    cudaGetSymbolAddress((void**)&w2h,  g_w2h);  cudaGetSymbolAddress((void**)&w2l,  g_w2l);

    int attn_smem = (4096 + 4096 + 128 * 65) * (int)sizeof(float);
    cudaFuncSetAttribute(k_attn, cudaFuncAttributeMaxDynamicSharedMemorySize, attn_smem);
    cudaFuncSetAttribute(k_mma_gemm<0,true,false,false>, cudaFuncAttributeMaxDynamicSharedMemorySize, GSMEM);
    cudaFuncSetAttribute(k_mma_gemm<2,false,true,false>, cudaFuncAttributeMaxDynamicSharedMemorySize, GSMEM);
    cudaFuncSetAttribute(k_mma_gemm<1,false,true,false>, cudaFuncAttributeMaxDynamicSharedMemorySize, GSMEM);
    cudaFuncSetAttribute(k_mma_gemm<0,true,false,true>,  cudaFuncAttributeMaxDynamicSharedMemorySize, GSMEM);

    dim3 wb(32, 8);
    k_wconv<<<dim3(PD/32,  PD/32),  wb>>>(wq,  wqh,  wql,  PD,   PD);
    k_wconv<<<dim3(PD/32,  PD/32),  wb>>>(wk,  wkh,  wkl,  PD,   PD);
    k_wconv<<<dim3(PD/32,  PD/32),  wb>>>(wv,  wvh,  wvl,  PD,   PD);
    k_wconv<<<dim3(PD/32,  PD/32),  wb>>>(wo,  woh,  wol,  PD,   PD);
    k_wconv<<<dim3(PDFF/32,PD/32),  wb>>>(wi,  wih,  wil,  PD,   PDFF);
    k_wconv<<<dim3(PD/32,  PDFF/32),wb>>>(wo2, wo2h, wo2l, PDFF, PD);
    k_wconv<<<dim3(PDFF/32,PD/32),  wb>>>(w1,  w1h,  w1l,  PD,   PDFF);
    k_wconv<<<dim3(PD/32,  PDFF/32),wb>>>(w2,  w2h,  w2l,  PDFF, PD);

    dim3 gD(PD / 128, NT / 128);
    dim3 gF(PDFF / 128, NT / 128);

    // 1. embed double-LN -> h (fp32 + bf16)
    k_embed<<<NT, 256>>>(src, pos, tt, n1s, n1b, embs, embb, p_h, hh, hl);
    // 2-4. QKV projections (fp32 out for attention)
    k_mma_gemm<0,true,false,false><<<gD, 256, GSMEM>>>(hh, hl, wqh, wql, bq, nullptr, p_q, nullptr, nullptr, NT, PD, PD, 0.125f);
    k_mma_gemm<0,true,false,false><<<gD, 256, GSMEM>>>(hh, hl, wkh, wkl, bk, nullptr, p_k, nullptr, nullptr, NT, PD, PD, 1.f);
    k_mma_gemm<0,true,false,false><<<gD, 256, GSMEM>>>(hh, hl, wvh, wvl, bv, nullptr, p_v, nullptr, nullptr, NT, PD, PD, 1.f);
    // 5. banded attention -> a (bf16 hi/lo)
    k_attn<<<dim3(2, PS / PW, PB * PH), 128, attn_smem>>>(p_q, p_k, p_v, aah, aal);
    // 6. attn out proj -> tmp fp32
    k_mma_gemm<0,true,false,false><<<gD, 256, GSMEM>>>(aah, aal, woh, wol, bo, nullptr, p_tmp, nullptr, nullptr, NT, PD, PD, 1.f);
    // 7. h2 = ln(h + tmp)
    k_add_ln<<<NT, 256>>>(p_h, p_tmp, atts, attb, 1e-12f, p_h2, h2h, h2l);
    // 8. FFN1 + GELU -> ff (bf16 only)
    k_mma_gemm<2,false,true,false><<<gF, 256, GSMEM>>>(h2h, h2l, wih, wil, bi, nullptr, nullptr, ffh, ffl, NT, PDFF, PD, 1.f);
    // 9. FFN2 -> tmp fp32
    k_mma_gemm<0,true,false,false><<<gD, 256, GSMEM>>>(ffh, ffl, wo2h, wo2l, bo2, nullptr, p_tmp, nullptr, nullptr, NT, PD, PDFF, 1.f);
    // 10. out-LN -> src2; n2-LN -> x (bf16)
    k_mid<<<NT, 256>>>(p_h2, p_tmp, outs, outb, src, n2s, n2b, p_src2, xh, xl);
    // 11. MLP1 + ReLU -> ff (bf16)
    k_mma_gemm<1,false,true,false><<<gF, 256, GSMEM>>>(xh, xl, w1h, w1l, b1, nullptr, nullptr, ffh, ffl, NT, PDFF, PD, 1.f);
    // 12. MLP2 + residual(src2) -> d_out
    k_mma_gemm<0,true,false,true><<<gD, 256, GSMEM>>>(ffh, ffl, w2h, w2l, b2, p_src2, out, nullptr, nullptr, NT, PD, PDFF, 1.f);
}